// round 1
// baseline (speedup 1.0000x reference)
#include <cuda_runtime.h>
#include <math.h>

// Shapes (fixed for this problem)
//   x:       (1024, 1, 63, 250) fp32   -> nodes (63, 256000), f = a*250 + d
//   W:       (256000, 256) fp32
//   att_src: (256,), att_dst: (256,), bias: (256,)
//   out:     (63, 1) fp32
#define NA     1024
#define NC     63
#define ND     250
#define NK     (NA * ND)       // 256000
#define NOUT   256
#define ROWS_PER_BLOCK_A 8

// ---- scratch (no allocations allowed) ----
__device__ float4 g_v4[NK];                 // (w·att_src, w·att_dst, row_mean_weight, pad)
__device__ float  g_partial[NC * 3 * NA];   // [(c*3+t)*1024 + a]
__device__ float  g_out3[NC * 3];           // reduced (a_src, a_dst, hbar) per node

// ============================================================================
// Kernel A: project each row of W onto {att_src, att_dst, ones/256}.
// One warp per row. Streams W (262 MB) exactly once. HBM-bound.
// ============================================================================
__global__ void __launch_bounds__(256) proj_w_kernel(
    const float* __restrict__ W,
    const float* __restrict__ att_src,
    const float* __restrict__ att_dst)
{
    const int warp = threadIdx.x >> 5;
    const int lane = threadIdx.x & 31;
    const int k    = blockIdx.x * ROWS_PER_BLOCK_A + warp;   // row of W

    const float4* __restrict__ Wr = reinterpret_cast<const float4*>(W) + (size_t)k * (NOUT / 4);
    const float4* __restrict__ s4 = reinterpret_cast<const float4*>(att_src);
    const float4* __restrict__ d4 = reinterpret_cast<const float4*>(att_dst);

    // lane covers cols [lane*4, lane*4+4) and [128+lane*4, 128+lane*4+4)
    float4 w0 = Wr[lane];
    float4 w1 = Wr[lane + 32];
    float4 a0 = s4[lane];
    float4 a1 = s4[lane + 32];
    float4 b0 = d4[lane];
    float4 b1 = d4[lane + 32];

    float ss = w0.x * a0.x + w0.y * a0.y + w0.z * a0.z + w0.w * a0.w
             + w1.x * a1.x + w1.y * a1.y + w1.z * a1.z + w1.w * a1.w;
    float sd = w0.x * b0.x + w0.y * b0.y + w0.z * b0.z + w0.w * b0.w
             + w1.x * b1.x + w1.y * b1.y + w1.z * b1.z + w1.w * b1.w;
    float sm = w0.x + w0.y + w0.z + w0.w + w1.x + w1.y + w1.z + w1.w;

    #pragma unroll
    for (int off = 16; off > 0; off >>= 1) {
        ss += __shfl_xor_sync(0xffffffffu, ss, off);
        sd += __shfl_xor_sync(0xffffffffu, sd, off);
        sm += __shfl_xor_sync(0xffffffffu, sm, off);
    }
    if (lane == 0) {
        g_v4[k] = make_float4(ss, sd, sm * (1.0f / 256.0f), 0.0f);
    }
}

// ============================================================================
// Kernel B: per batch index a, accumulate the 63 nodes' dot products with the
// projected weight slice v[a*250 .. a*250+250). v slice cached in SMEM and
// reused across all 63 nodes (avoids re-streaming v per node).
// Streams x (64.5 MB) exactly once. Deterministic partial sums to scratch.
// ============================================================================
__global__ void __launch_bounds__(256) nodes_kernel(const float* __restrict__ x)
{
    __shared__ float4 sv[ND];
    const int a = blockIdx.x;

    for (int d = threadIdx.x; d < ND; d += blockDim.x)
        sv[d] = g_v4[a * ND + d];
    __syncthreads();

    const int warp = threadIdx.x >> 5;
    const int lane = threadIdx.x & 31;
    const float* __restrict__ xa = x + (size_t)a * (NC * ND);

    for (int c = warp; c < NC; c += 8) {
        const float* __restrict__ xr = xa + c * ND;
        float s0 = 0.f, s1 = 0.f, s2 = 0.f;
        for (int d = lane; d < ND; d += 32) {
            float  xv = xr[d];
            float4 v  = sv[d];
            s0 = fmaf(xv, v.x, s0);
            s1 = fmaf(xv, v.y, s1);
            s2 = fmaf(xv, v.z, s2);
        }
        #pragma unroll
        for (int off = 16; off > 0; off >>= 1) {
            s0 += __shfl_xor_sync(0xffffffffu, s0, off);
            s1 += __shfl_xor_sync(0xffffffffu, s1, off);
            s2 += __shfl_xor_sync(0xffffffffu, s2, off);
        }
        if (lane == 0) {
            g_partial[(c * 3 + 0) * NA + a] = s0;
            g_partial[(c * 3 + 1) * NA + a] = s1;
            g_partial[(c * 3 + 2) * NA + a] = s2;
        }
    }
}

// ============================================================================
// Kernel C: reduce the 1024 batch-partials for each of the 189 (c,t) slots.
// ============================================================================
__global__ void __launch_bounds__(256) reduce_kernel()
{
    const int b = blockIdx.x;                 // 0 .. 188
    const float* __restrict__ p = g_partial + b * NA;

    float s = 0.f;
    for (int i = threadIdx.x; i < NA; i += 256) s += p[i];

    __shared__ float sh[256];
    sh[threadIdx.x] = s;
    __syncthreads();
    for (int st = 128; st > 0; st >>= 1) {
        if (threadIdx.x < st) sh[threadIdx.x] += sh[threadIdx.x + st];
        __syncthreads();
    }
    if (threadIdx.x == 0) g_out3[b] = sh[0];
}

// ============================================================================
// Kernel D: 63x63 dense leaky-relu softmax + weighted aggregation + bias mean.
// ============================================================================
__global__ void __launch_bounds__(64) softmax_kernel(
    const float* __restrict__ bias, float* __restrict__ out)
{
    __shared__ float as_[NC], ad_[NC], hb_[NC];
    __shared__ float bm;
    const int t = threadIdx.x;

    if (t < NC) {
        as_[t] = g_out3[t * 3 + 0];
        ad_[t] = g_out3[t * 3 + 1];
        hb_[t] = g_out3[t * 3 + 2];
    }
    if (t == 0) {
        float s = 0.f;
        for (int i = 0; i < NOUT; i++) s += bias[i];
        bm = s * (1.0f / 256.0f);
    }
    __syncthreads();

    if (t < NC) {
        const float ai = ad_[t];
        float m = -1e30f;
        for (int j = 0; j < NC; j++) {
            float e = ai + as_[j];
            e = (e > 0.f) ? e : 0.2f * e;
            m = fmaxf(m, e);
        }
        float Z = 0.f, S = 0.f;
        for (int j = 0; j < NC; j++) {
            float e = ai + as_[j];
            e = (e > 0.f) ? e : 0.2f * e;
            float w = expf(e - m);
            Z += w;
            S = fmaf(w, hb_[j], S);
        }
        out[t] = S / Z + bm;
    }
}

// ============================================================================
extern "C" void kernel_launch(void* const* d_in, const int* in_sizes, int n_in,
                              void* d_out, int out_size)
{
    const float* x       = (const float*)d_in[0];
    const float* W       = (const float*)d_in[1];
    const float* att_src = (const float*)d_in[2];
    const float* att_dst = (const float*)d_in[3];
    const float* bias    = (const float*)d_in[4];
    float* out = (float*)d_out;

    proj_w_kernel<<<NK / ROWS_PER_BLOCK_A, 256>>>(W, att_src, att_dst);
    nodes_kernel<<<NA, 256>>>(x);
    reduce_kernel<<<NC * 3, 256>>>();
    softmax_kernel<<<1, 64>>>(bias, out);
}